// round 15
// baseline (speedup 1.0000x reference)
#include <cuda_runtime.h>
#include <cstdint>

#define GRID   296
#define BLOCK  256
#define NE     8
#define HDIM   1024
#define DEPTH  4            // cp.async pipeline stages (chunks in flight)

#define SW_BYTES     (NE * HDIM * 4)            // 32 KB weights
#define STAGE_BYTES  2048                       // one chunk: 4 tokens x 512B
#define WSTAGE_BYTES (DEPTH * STAGE_BYTES)      // 8 KB per warp
#define DYN_SMEM     (SW_BYTES + (BLOCK / 32) * WSTAGE_BYTES)   // 96 KB

__device__ float g_partials[GRID * 16];
__device__ int   g_ticket = 0;

// Packed fp32x2 FMA (Blackwell): d.lo += a.lo*b.lo ; d.hi += a.hi*b.hi
#define FMA2(d, a, b) asm("fma.rn.f32x2 %0, %1, %2, %0;" : "+l"(d) : "l"(a), "l"(b))

#define CP_COMMIT()  asm volatile("cp.async.commit_group;" ::: "memory")
#define CP_WAIT(n)   asm volatile("cp.async.wait_group %0;" :: "n"(n) : "memory")

__device__ __forceinline__ uint32_t smem_u32(const void* p) {
    return (uint32_t)__cvta_generic_to_shared(p);
}

// stage chunk c of a group (4 tokens): lane L copies its own 16B per token.
__device__ __forceinline__ void issue_chunk(uint32_t stage_w, const ulonglong2* h0,
                                            int c, int lane)
{
    const uint32_t dst = stage_w + (c & (DEPTH - 1)) * STAGE_BYTES + lane * 16;
    const ulonglong2* src = h0 + c * 32 + lane;
    #pragma unroll
    for (int t = 0; t < 4; t++)
        asm volatile("cp.async.cg.shared.global [%0], [%1], 16;"
                     :: "r"(dst + t * 512), "l"(src + t * (HDIM / 4)));
    CP_COMMIT();
}

__device__ __forceinline__ void suffix_scan256(int* h, int n)
{
    for (int off = 1; off < n; off <<= 1) {
        int v[8]; int c = 0;
        for (int i = threadIdx.x; i < n; i += BLOCK) {
            const int add = (i + off < n) ? h[i + off] : 0;
            v[c++] = h[i] + add;
        }
        __syncthreads();
        c = 0;
        for (int i = threadIdx.x; i < n; i += BLOCK) h[i] = v[c++];
        __syncthreads();
    }
}

__global__ void __launch_bounds__(BLOCK, 2)
route_fused(const float* __restrict__ hs, const float* __restrict__ rw,
            float* __restrict__ disp, float* __restrict__ probs,
            float* __restrict__ loss_out, int ntok)
{
    extern __shared__ __align__(16) char dynsmem[];
    float* sw = (float*)dynsmem;                           // 32 KB weights / finalize hist
    char*  hstage = dynsmem + SW_BYTES;                    // 64 KB cp.async stages

    __shared__ float sW[BLOCK / 32][NE];
    __shared__ float sP[BLOCK / 32][NE];
    __shared__ float red[BLOCK / 32][16];
    __shared__ float sSum[16];
    __shared__ int   s_best, s_tiecnt, s_last;
    __shared__ unsigned s_over;

    // Stage router weights (32KB) into SMEM
    {
        const float4* src = (const float4*)rw;
        float4* dst = (float4*)sw;
        for (int i = threadIdx.x; i < NE * HDIM / 4; i += BLOCK) dst[i] = src[i];
    }
    __syncthreads();

    const int warp = threadIdx.x >> 5;
    const int lane = threadIdx.x & 31;
    const int gwarp = blockIdx.x * (BLOCK / 32) + warp;
    const int nwarps = GRID * (BLOCK / 32);
    const int ngroups = (ntok + 3) >> 2;      // 4 tokens per warp-iteration

    const ulonglong2* __restrict__ hs2 = (const ulonglong2*)hs;  // 256 x 16B per row
    const ulonglong2* __restrict__ w2  = (const ulonglong2*)sw;

    // this warp's staging ring: SMEM address (for cp.async) + C++ pointer (for loads)
    char* const stage_base = hstage + warp * WSTAGE_BYTES;
    const uint32_t stage_w = smem_u32(stage_base);

    float accW = 0.f;
    float accP = 0.f;

    // ---- pipeline prologue: issue first group's chunks 0..DEPTH-1 ----
    {
        const bool act = (gwarp < ngroups) && (((gwarp << 2) + 4) <= ntok);
        const ulonglong2* h0p = hs2 + (size_t)(gwarp << 2) * (HDIM / 4);
        #pragma unroll
        for (int d = 0; d < DEPTH; d++) {
            if (act) issue_chunk(stage_w, h0p, d, lane);
            else     CP_COMMIT();
        }
    }

    for (int g = gwarp; g < ngroups; g += nwarps) {
        const int t0 = g << 2;
        const int tcount = (t0 + 4 <= ntok) ? 4 : (ntok - t0);

        unsigned long long acc[4][NE];    // 64 regs
        #pragma unroll
        for (int t = 0; t < 4; t++)
            #pragma unroll
            for (int e = 0; e < NE; e++) acc[t][e] = 0ull;

        const ulonglong2* __restrict__ h0 = hs2 + (size_t)t0 * (HDIM / 4);

        if (tcount == 4) {
            const int gn = g + nwarps;
            const bool nfull = (gn < ngroups) && (((gn << 2) + 4) <= ntok);
            const ulonglong2* __restrict__ hn = hs2 + (size_t)(gn << 2) * (HDIM / 4);

            #pragma unroll
            for (int c = 0; c < HDIM / 128; c++) {
                CP_WAIT(DEPTH - 1);     // oldest pending group (this chunk) complete

                // plain C++ shared loads: ordered after CP_WAIT and before the next
                // volatile cp.async by the "memory" clobbers (the R14 bug was using
                // non-volatile asm here, which the compiler hoisted above the wait).
                const ulonglong2* sp = (const ulonglong2*)(
                    stage_base + (c & (DEPTH - 1)) * STAGE_BYTES + lane * 16);
                ulonglong2 h[4];
                #pragma unroll
                for (int t = 0; t < 4; t++) h[t] = sp[t * 32];   // t*512 bytes

                const int off = c * 32 + lane;
                #pragma unroll
                for (int e = 0; e < NE; e++) {
                    const ulonglong2 w = w2[e * (HDIM / 4) + off];
                    #pragma unroll
                    for (int t = 0; t < 4; t++) {
                        FMA2(acc[t][e], h[t].x, w.x);
                        FMA2(acc[t][e], h[t].y, w.y);
                    }
                }

                // refill slot just consumed: this group's chunk c+4, or next group's c-4
                if (c + DEPTH < HDIM / 128)      issue_chunk(stage_w, h0, c + DEPTH, lane);
                else if (nfull)                  issue_chunk(stage_w, hn, c + DEPTH - HDIM / 128, lane);
                else                             CP_COMMIT();
            }

            // lo+hi combine: a[k] = partial logit of value k = t*8+e
            float a[32];
            #pragma unroll
            for (int t = 0; t < 4; t++)
                #pragma unroll
                for (int e = 0; e < NE; e++) {
                    const unsigned long long v = acc[t][e];
                    a[t * NE + e] = __uint_as_float((unsigned)v) +
                                    __uint_as_float((unsigned)(v >> 32));
                }

            // transpose-reduce (bit-identical to per-value butterfly; proven R12/13)
            #pragma unroll
            for (int s = 16; s > 0; s >>= 1) {
                const bool hi = (lane & s) != 0;
                #pragma unroll
                for (int j = 0; j < 32; j++) {
                    if (j >= s) break;
                    const float give = hi ? a[j] : a[j + s];
                    const float got  = __shfl_xor_sync(0xffffffffu, give, s);
                    const float keep = hi ? a[j + s] : a[j];
                    a[j] = keep + got;
                }
            }
            const float l_own = a[0];
            const int   e_own = lane & 7;
            const int   base  = lane & ~7;

            float ls[NE];
            #pragma unroll
            for (int e = 0; e < NE; e++)
                ls[e] = __shfl_sync(0xffffffffu, l_own, base | e);
            float mx = ls[0];
            #pragma unroll
            for (int e = 1; e < NE; e++) mx = fmaxf(mx, ls[e]);

            const float ex_own = expf(l_own - mx);
            float ex[NE], sum = 0.f;
            #pragma unroll
            for (int e = 0; e < NE; e++) {
                ex[e] = __shfl_sync(0xffffffffu, ex_own, base | e);
                sum += ex[e];
            }
            const float inv = 1.f / sum;
            float p[NE];
            #pragma unroll
            for (int e = 0; e < NE; e++) p[e] = ex[e] * inv;

            int i1 = 0;
            #pragma unroll
            for (int e = 1; e < NE; e++) if (p[e] > p[i1]) i1 = e;
            int i2 = -1;
            #pragma unroll
            for (int e = 0; e < NE; e++)
                if (e != i1 && (i2 < 0 || p[e] > p[i2])) i2 = e;
            const float dsum = p[i1] + p[i2];
            const float d1 = p[i1] / dsum;
            const float d2 = p[i2] / dsum;

            const float p_own = p[e_own];
            const float dm = (e_own == i1) ? d1 : (e_own == i2) ? d2 : 0.f;
            const size_t o = (size_t)t0 * NE + lane;
            probs[o] = p_own;
            disp[o]  = dm;
            accP += p_own;
            accW += dm;
        } else {
            // tail (<4 tokens): drain pipeline, direct-LDG path (same per-token math)
            CP_WAIT(0);
            for (int c = 0; c < HDIM / 128; c++) {
                const int off = c * 32 + lane;
                for (int t = 0; t < tcount; t++) {
                    const ulonglong2 h = h0[t * (HDIM / 4) + off];
                    #pragma unroll
                    for (int e = 0; e < NE; e++) {
                        const ulonglong2 w = w2[e * (HDIM / 4) + off];
                        FMA2(acc[t][e], h.x, w.x);
                        FMA2(acc[t][e], h.y, w.y);
                    }
                }
            }
            for (int t = 0; t < tcount; t++) {
                float l[NE];
                #pragma unroll
                for (int e = 0; e < NE; e++) {
                    const unsigned long long v = acc[t][e];
                    l[e] = __uint_as_float((unsigned)v) + __uint_as_float((unsigned)(v >> 32));
                }
                #pragma unroll
                for (int s = 16; s > 0; s >>= 1)
                    #pragma unroll
                    for (int e = 0; e < NE; e++)
                        l[e] += __shfl_xor_sync(0xffffffffu, l[e], s);
                float mx = l[0];
                #pragma unroll
                for (int e = 1; e < NE; e++) mx = fmaxf(mx, l[e]);
                float ex[NE], sum = 0.f;
                #pragma unroll
                for (int e = 0; e < NE; e++) { ex[e] = expf(l[e] - mx); sum += ex[e]; }
                const float inv = 1.f / sum;
                float p[NE];
                #pragma unroll
                for (int e = 0; e < NE; e++) p[e] = ex[e] * inv;
                int i1 = 0;
                #pragma unroll
                for (int e = 1; e < NE; e++) if (p[e] > p[i1]) i1 = e;
                int i2 = -1;
                #pragma unroll
                for (int e = 0; e < NE; e++)
                    if (e != i1 && (i2 < 0 || p[e] > p[i2])) i2 = e;
                const float dsum = p[i1] + p[i2];
                const float d1 = p[i1] / dsum;
                const float d2 = p[i2] / dsum;
                if (lane < NE) {
                    const size_t o = (size_t)(t0 + t) * NE + lane;
                    probs[o] = p[lane];
                    const float dm = (lane == i1) ? d1 : (lane == i2) ? d2 : 0.f;
                    disp[o] = dm;
                    accP += p[lane];
                    accW += dm;
                }
            }
        }
    }
    CP_WAIT(0);   // drain any trailing groups

    // combine lanes sharing the same expert (xor over token bits 3,4)
    accW += __shfl_xor_sync(0xffffffffu, accW, 8);
    accW += __shfl_xor_sync(0xffffffffu, accW, 16);
    accP += __shfl_xor_sync(0xffffffffu, accP, 8);
    accP += __shfl_xor_sync(0xffffffffu, accP, 16);

    if (lane < NE) { sW[warp][lane] = accW; sP[warp][lane] = accP; }
    __syncthreads();
    if (threadIdx.x < 16) {
        const int e = threadIdx.x & 7;
        float s = 0.f;
        if (threadIdx.x < 8) {
            #pragma unroll
            for (int w = 0; w < BLOCK / 32; w++) s += sW[w][e];
        } else {
            #pragma unroll
            for (int w = 0; w < BLOCK / 32; w++) s += sP[w][e];
        }
        g_partials[blockIdx.x * 16 + threadIdx.x] = s;
    }
    __syncthreads();

    // ---- last-block election ----
    if (threadIdx.x == 0) {
        __threadfence();
        const int old = atomicAdd(&g_ticket, 1);
        s_last = (old == GRID - 1);
        if (s_last) g_ticket = 0;
    }
    __syncthreads();
    if (!s_last) return;

    // =================== finalize (last block only, 256 threads) ===================
    const int tid = threadIdx.x;
    int* hist = (int*)sw;            // weights no longer needed: reuse as hist/ties
    {
        float s = 0.f;
        for (int i = tid; i < GRID * 16; i += BLOCK) s += g_partials[i];
        s += __shfl_xor_sync(0xffffffffu, s, 16);
        if (lane < 16) red[warp][lane] = s;
    }
    __syncthreads();
    if (tid < 16) {
        float s = 0.f;
        #pragma unroll
        for (int w = 0; w < BLOCK / 32; w++) s += red[w][tid];
        sSum[tid] = s;
    }
    __syncthreads();

    const int cap = (int)(1.25 * (double)ntok / (double)NE);

    if (tid == 0) {
        float l = 0.f;
        for (int e = 0; e < NE; e++) l += sSum[e] * sSum[8 + e];
        loss_out[0] = 0.01f * (l / (float)ntok);
        unsigned m = 0;
        for (int e = 0; e < NE; e++)
            if (sSum[e] > (float)cap) m |= 1u << e;
        s_over = m;
    }
    __syncthreads();
    const unsigned over = s_over;
    if (!over) return;

    for (int e = 0; e < NE; e++) {
        if (!((over >> e) & 1u)) continue;

        for (int i = tid; i < 2048; i += BLOCK) hist[i] = 0;
        __syncthreads();
        for (int t = tid; t < ntok; t += BLOCK) {
            const float v = disp[(size_t)t * NE + e];
            if (v > 0.f) atomicAdd(&hist[__float_as_uint(v) >> 20], 1);
        }
        __syncthreads();
        suffix_scan256(hist, 2048);
        if (tid == 0) s_best = -1;
        __syncthreads();
        for (int i = tid; i < 2048; i += BLOCK)
            if (hist[i] >= cap) atomicMax(&s_best, i);
        __syncthreads();
        const int b1 = s_best;
        if (b1 < 0) { __syncthreads(); continue; }
        const int A1 = (b1 + 1 < 2048) ? hist[b1 + 1] : 0;
        const int cap2 = cap - A1;
        __syncthreads();

        for (int i = tid; i < 2048; i += BLOCK) hist[i] = 0;
        __syncthreads();
        for (int t = tid; t < ntok; t += BLOCK) {
            const float v = disp[(size_t)t * NE + e];
            if (v > 0.f) {
                const unsigned b = __float_as_uint(v);
                if ((int)(b >> 20) == b1) atomicAdd(&hist[(b >> 9) & 0x7FF], 1);
            }
        }
        __syncthreads();
        suffix_scan256(hist, 2048);
        if (tid == 0) s_best = -1;
        __syncthreads();
        for (int i = tid; i < 2048; i += BLOCK)
            if (hist[i] >= cap2) atomicMax(&s_best, i);
        __syncthreads();
        const int b2 = s_best;
        const int A2 = (b2 + 1 < 2048) ? hist[b2 + 1] : 0;
        const int cap3 = cap2 - A2;
        const unsigned key = ((unsigned)b1 << 11) | (unsigned)b2;
        __syncthreads();

        for (int i = tid; i < 512; i += BLOCK) hist[i] = 0;
        __syncthreads();
        for (int t = tid; t < ntok; t += BLOCK) {
            const float v = disp[(size_t)t * NE + e];
            if (v > 0.f) {
                const unsigned b = __float_as_uint(v);
                if ((b >> 9) == key) atomicAdd(&hist[b & 0x1FF], 1);
            }
        }
        __syncthreads();
        suffix_scan256(hist, 512);
        if (tid == 0) s_best = -1;
        __syncthreads();
        for (int i = tid; i < 512; i += BLOCK)
            if (hist[i] >= cap3) atomicMax(&s_best, i);
        __syncthreads();
        const int b3 = s_best;
        const int A3 = (b3 + 1 < 512) ? hist[b3 + 1] : 0;
        const int keep_eq = cap3 - A3;
        const unsigned thr = (key << 9) | (unsigned)b3;
        __syncthreads();

        int* s_ties = hist;
        if (tid == 0) s_tiecnt = 0;
        __syncthreads();
        for (int t = tid; t < ntok; t += BLOCK) {
            const size_t o = (size_t)t * NE + e;
            const float v = disp[o];
            if (v > 0.f) {
                const unsigned b = __float_as_uint(v);
                if (b < thr) {
                    disp[o] = 0.f;
                } else if (b == thr) {
                    const int p = atomicAdd(&s_tiecnt, 1);
                    if (p < 2048) s_ties[p] = t;
                }
            }
        }
        __syncthreads();
        const int tc = (s_tiecnt < 2048) ? s_tiecnt : 2048;
        if (s_tiecnt > keep_eq) {
            for (int i = tid; i < tc; i += BLOCK) {
                const int ti = s_ties[i];
                int rank = 0;
                for (int j = 0; j < tc; j++) rank += (s_ties[j] < ti);
                if (rank >= keep_eq) disp[(size_t)ti * NE + e] = 0.f;
            }
        }
        __syncthreads();
    }
}

extern "C" void kernel_launch(void* const* d_in, const int* in_sizes, int n_in,
                              void* d_out, int out_size)
{
    const float* hs = (const float*)d_in[0];
    const float* rw = (const float*)d_in[1];
    int hsize = in_sizes[0];
    if (n_in >= 2 && in_sizes[0] < in_sizes[1]) {
        hs = (const float*)d_in[1];
        rw = (const float*)d_in[0];
        hsize = in_sizes[1];
    }
    const int ntok = hsize / HDIM;

    float* out   = (float*)d_out;
    float* disp  = out;                          // [N, E]
    float* loss  = out + (size_t)ntok * NE;      // scalar
    float* probs = loss + 1;                     // [N, E]

    cudaFuncSetAttribute(route_fused, cudaFuncAttributeMaxDynamicSharedMemorySize, DYN_SMEM);
    route_fused<<<GRID, BLOCK, DYN_SMEM>>>(hs, rw, disp, probs, loss, ntok);
}

// round 16
// speedup vs baseline: 1.0400x; 1.0400x over previous
#include <cuda_runtime.h>
#include <cuda_pipeline_primitives.h>
#include <cstdint>

#define GRID   296
#define BLOCK  256
#define NE     8
#define HDIM   1024
#define DEPTH  4            // cp.async pipeline stages (chunks in flight)

#define SW_BYTES     (NE * HDIM * 4)            // 32 KB weights
#define STAGE_BYTES  2048                       // one chunk: 4 tokens x 512B
#define WSTAGE_BYTES (DEPTH * STAGE_BYTES)      // 8 KB per warp
#define DYN_SMEM     (SW_BYTES + (BLOCK / 32) * WSTAGE_BYTES)   // 96 KB

__device__ float g_partials[GRID * 16];
__device__ int   g_ticket = 0;

// Packed fp32x2 FMA (Blackwell): d.lo += a.lo*b.lo ; d.hi += a.hi*b.hi
#define FMA2(d, a, b) asm("fma.rn.f32x2 %0, %1, %2, %0;" : "+l"(d) : "l"(a), "l"(b))

// stage chunk c of a group (4 tokens): lane L copies its own 16B per token.
// Intrinsic form: compiler keeps full aliasing info (no memory clobbers), so
// weight loads stay register-cached and copies from successive chunks overlap.
__device__ __forceinline__ void issue_chunk(char* stage_base, const ulonglong2* h0,
                                            int c, int lane)
{
    char* dst = stage_base + (c & (DEPTH - 1)) * STAGE_BYTES + lane * 16;
    const ulonglong2* src = h0 + c * 32 + lane;
    #pragma unroll
    for (int t = 0; t < 4; t++)
        __pipeline_memcpy_async(dst + t * 512, src + t * (HDIM / 4), 16);
    __pipeline_commit();
}

__device__ __forceinline__ void suffix_scan256(int* h, int n)
{
    for (int off = 1; off < n; off <<= 1) {
        int v[8]; int c = 0;
        for (int i = threadIdx.x; i < n; i += BLOCK) {
            const int add = (i + off < n) ? h[i + off] : 0;
            v[c++] = h[i] + add;
        }
        __syncthreads();
        c = 0;
        for (int i = threadIdx.x; i < n; i += BLOCK) h[i] = v[c++];
        __syncthreads();
    }
}

__global__ void __launch_bounds__(BLOCK, 2)
route_fused(const float* __restrict__ hs, const float* __restrict__ rw,
            float* __restrict__ disp, float* __restrict__ probs,
            float* __restrict__ loss_out, int ntok)
{
    extern __shared__ __align__(16) char dynsmem[];
    float* sw = (float*)dynsmem;                           // 32 KB weights / finalize hist
    char*  hstage = dynsmem + SW_BYTES;                    // 64 KB cp.async stages

    __shared__ float sW[BLOCK / 32][NE];
    __shared__ float sP[BLOCK / 32][NE];
    __shared__ float red[BLOCK / 32][16];
    __shared__ float sSum[16];
    __shared__ int   s_best, s_tiecnt, s_last;
    __shared__ unsigned s_over;

    // Stage router weights (32KB) into SMEM
    {
        const float4* src = (const float4*)rw;
        float4* dst = (float4*)sw;
        for (int i = threadIdx.x; i < NE * HDIM / 4; i += BLOCK) dst[i] = src[i];
    }
    __syncthreads();

    const int warp = threadIdx.x >> 5;
    const int lane = threadIdx.x & 31;
    const int gwarp = blockIdx.x * (BLOCK / 32) + warp;
    const int nwarps = GRID * (BLOCK / 32);
    const int ngroups = (ntok + 3) >> 2;      // 4 tokens per warp-iteration

    const ulonglong2* __restrict__ hs2 = (const ulonglong2*)hs;  // 256 x 16B per row
    const ulonglong2* __restrict__ w2  = (const ulonglong2*)sw;

    char* const stage_base = hstage + warp * WSTAGE_BYTES;

    float accW = 0.f;
    float accP = 0.f;

    // ---- pipeline prologue: issue first group's chunks 0..DEPTH-1 ----
    {
        const bool act = (gwarp < ngroups) && (((gwarp << 2) + 4) <= ntok);
        const ulonglong2* h0p = hs2 + (size_t)(gwarp << 2) * (HDIM / 4);
        #pragma unroll
        for (int d = 0; d < DEPTH; d++) {
            if (act) issue_chunk(stage_base, h0p, d, lane);
            else     __pipeline_commit();
        }
    }

    for (int g = gwarp; g < ngroups; g += nwarps) {
        const int t0 = g << 2;
        const int tcount = (t0 + 4 <= ntok) ? 4 : (ntok - t0);

        unsigned long long acc[4][NE];    // 64 regs
        #pragma unroll
        for (int t = 0; t < 4; t++)
            #pragma unroll
            for (int e = 0; e < NE; e++) acc[t][e] = 0ull;

        const ulonglong2* __restrict__ h0 = hs2 + (size_t)t0 * (HDIM / 4);

        if (tcount == 4) {
            const int gn = g + nwarps;
            const bool nfull = (gn < ngroups) && (((gn << 2) + 4) <= ntok);
            const ulonglong2* __restrict__ hn = hs2 + (size_t)(gn << 2) * (HDIM / 4);

            #pragma unroll
            for (int c = 0; c < HDIM / 128; c++) {
                __pipeline_wait_prior(DEPTH - 1);   // this chunk's copy complete

                const ulonglong2* sp = (const ulonglong2*)(
                    stage_base + (c & (DEPTH - 1)) * STAGE_BYTES + lane * 16);
                ulonglong2 h[4];
                #pragma unroll
                for (int t = 0; t < 4; t++) h[t] = sp[t * 32];   // t*512 bytes

                const int off = c * 32 + lane;
                #pragma unroll
                for (int e = 0; e < NE; e++) {
                    const ulonglong2 w = w2[e * (HDIM / 4) + off];
                    #pragma unroll
                    for (int t = 0; t < 4; t++) {
                        FMA2(acc[t][e], h[t].x, w.x);
                        FMA2(acc[t][e], h[t].y, w.y);
                    }
                }

                // refill slot just consumed: this group's chunk c+4, or next group's c-4
                if (c + DEPTH < HDIM / 128)      issue_chunk(stage_base, h0, c + DEPTH, lane);
                else if (nfull)                  issue_chunk(stage_base, hn, c + DEPTH - HDIM / 128, lane);
                else                             __pipeline_commit();
            }

            // lo+hi combine: a[k] = partial logit of value k = t*8+e
            float a[32];
            #pragma unroll
            for (int t = 0; t < 4; t++)
                #pragma unroll
                for (int e = 0; e < NE; e++) {
                    const unsigned long long v = acc[t][e];
                    a[t * NE + e] = __uint_as_float((unsigned)v) +
                                    __uint_as_float((unsigned)(v >> 32));
                }

            // transpose-reduce (bit-identical to per-value butterfly; proven R12/13)
            #pragma unroll
            for (int s = 16; s > 0; s >>= 1) {
                const bool hi = (lane & s) != 0;
                #pragma unroll
                for (int j = 0; j < 32; j++) {
                    if (j >= s) break;
                    const float give = hi ? a[j] : a[j + s];
                    const float got  = __shfl_xor_sync(0xffffffffu, give, s);
                    const float keep = hi ? a[j + s] : a[j];
                    a[j] = keep + got;
                }
            }
            const float l_own = a[0];
            const int   e_own = lane & 7;
            const int   base  = lane & ~7;

            float ls[NE];
            #pragma unroll
            for (int e = 0; e < NE; e++)
                ls[e] = __shfl_sync(0xffffffffu, l_own, base | e);
            float mx = ls[0];
            #pragma unroll
            for (int e = 1; e < NE; e++) mx = fmaxf(mx, ls[e]);

            const float ex_own = expf(l_own - mx);
            float ex[NE], sum = 0.f;
            #pragma unroll
            for (int e = 0; e < NE; e++) {
                ex[e] = __shfl_sync(0xffffffffu, ex_own, base | e);
                sum += ex[e];
            }
            const float inv = 1.f / sum;
            float p[NE];
            #pragma unroll
            for (int e = 0; e < NE; e++) p[e] = ex[e] * inv;

            int i1 = 0;
            #pragma unroll
            for (int e = 1; e < NE; e++) if (p[e] > p[i1]) i1 = e;
            int i2 = -1;
            #pragma unroll
            for (int e = 0; e < NE; e++)
                if (e != i1 && (i2 < 0 || p[e] > p[i2])) i2 = e;
            const float dsum = p[i1] + p[i2];
            const float d1 = p[i1] / dsum;
            const float d2 = p[i2] / dsum;

            const float p_own = p[e_own];
            const float dm = (e_own == i1) ? d1 : (e_own == i2) ? d2 : 0.f;
            const size_t o = (size_t)t0 * NE + lane;
            probs[o] = p_own;
            disp[o]  = dm;
            accP += p_own;
            accW += dm;
        } else {
            // tail (<4 tokens): drain pipeline, direct-LDG path (same per-token math)
            __pipeline_wait_prior(0);
            for (int c = 0; c < HDIM / 128; c++) {
                const int off = c * 32 + lane;
                for (int t = 0; t < tcount; t++) {
                    const ulonglong2 h = h0[t * (HDIM / 4) + off];
                    #pragma unroll
                    for (int e = 0; e < NE; e++) {
                        const ulonglong2 w = w2[e * (HDIM / 4) + off];
                        FMA2(acc[t][e], h.x, w.x);
                        FMA2(acc[t][e], h.y, w.y);
                    }
                }
            }
            for (int t = 0; t < tcount; t++) {
                float l[NE];
                #pragma unroll
                for (int e = 0; e < NE; e++) {
                    const unsigned long long v = acc[t][e];
                    l[e] = __uint_as_float((unsigned)v) + __uint_as_float((unsigned)(v >> 32));
                }
                #pragma unroll
                for (int s = 16; s > 0; s >>= 1)
                    #pragma unroll
                    for (int e = 0; e < NE; e++)
                        l[e] += __shfl_xor_sync(0xffffffffu, l[e], s);
                float mx = l[0];
                #pragma unroll
                for (int e = 1; e < NE; e++) mx = fmaxf(mx, l[e]);
                float ex[NE], sum = 0.f;
                #pragma unroll
                for (int e = 0; e < NE; e++) { ex[e] = expf(l[e] - mx); sum += ex[e]; }
                const float inv = 1.f / sum;
                float p[NE];
                #pragma unroll
                for (int e = 0; e < NE; e++) p[e] = ex[e] * inv;
                int i1 = 0;
                #pragma unroll
                for (int e = 1; e < NE; e++) if (p[e] > p[i1]) i1 = e;
                int i2 = -1;
                #pragma unroll
                for (int e = 0; e < NE; e++)
                    if (e != i1 && (i2 < 0 || p[e] > p[i2])) i2 = e;
                const float dsum = p[i1] + p[i2];
                const float d1 = p[i1] / dsum;
                const float d2 = p[i2] / dsum;
                if (lane < NE) {
                    const size_t o = (size_t)(t0 + t) * NE + lane;
                    probs[o] = p[lane];
                    const float dm = (lane == i1) ? d1 : (lane == i2) ? d2 : 0.f;
                    disp[o] = dm;
                    accP += p[lane];
                    accW += dm;
                }
            }
        }
    }
    __pipeline_wait_prior(0);   // drain trailing groups

    // combine lanes sharing the same expert (xor over token bits 3,4)
    accW += __shfl_xor_sync(0xffffffffu, accW, 8);
    accW += __shfl_xor_sync(0xffffffffu, accW, 16);
    accP += __shfl_xor_sync(0xffffffffu, accP, 8);
    accP += __shfl_xor_sync(0xffffffffu, accP, 16);

    if (lane < NE) { sW[warp][lane] = accW; sP[warp][lane] = accP; }
    __syncthreads();
    if (threadIdx.x < 16) {
        const int e = threadIdx.x & 7;
        float s = 0.f;
        if (threadIdx.x < 8) {
            #pragma unroll
            for (int w = 0; w < BLOCK / 32; w++) s += sW[w][e];
        } else {
            #pragma unroll
            for (int w = 0; w < BLOCK / 32; w++) s += sP[w][e];
        }
        g_partials[blockIdx.x * 16 + threadIdx.x] = s;
    }
    __syncthreads();

    // ---- last-block election ----
    if (threadIdx.x == 0) {
        __threadfence();
        const int old = atomicAdd(&g_ticket, 1);
        s_last = (old == GRID - 1);
        if (s_last) g_ticket = 0;
    }
    __syncthreads();
    if (!s_last) return;

    // =================== finalize (last block only, 256 threads) ===================
    const int tid = threadIdx.x;
    int* hist = (int*)sw;            // weights no longer needed: reuse as hist/ties
    {
        float s = 0.f;
        for (int i = tid; i < GRID * 16; i += BLOCK) s += g_partials[i];
        s += __shfl_xor_sync(0xffffffffu, s, 16);
        if (lane < 16) red[warp][lane] = s;
    }
    __syncthreads();
    if (tid < 16) {
        float s = 0.f;
        #pragma unroll
        for (int w = 0; w < BLOCK / 32; w++) s += red[w][tid];
        sSum[tid] = s;
    }
    __syncthreads();

    const int cap = (int)(1.25 * (double)ntok / (double)NE);

    if (tid == 0) {
        float l = 0.f;
        for (int e = 0; e < NE; e++) l += sSum[e] * sSum[8 + e];
        loss_out[0] = 0.01f * (l / (float)ntok);
        unsigned m = 0;
        for (int e = 0; e < NE; e++)
            if (sSum[e] > (float)cap) m |= 1u << e;
        s_over = m;
    }
    __syncthreads();
    const unsigned over = s_over;
    if (!over) return;

    for (int e = 0; e < NE; e++) {
        if (!((over >> e) & 1u)) continue;

        for (int i = tid; i < 2048; i += BLOCK) hist[i] = 0;
        __syncthreads();
        for (int t = tid; t < ntok; t += BLOCK) {
            const float v = disp[(size_t)t * NE + e];
            if (v > 0.f) atomicAdd(&hist[__float_as_uint(v) >> 20], 1);
        }
        __syncthreads();
        suffix_scan256(hist, 2048);
        if (tid == 0) s_best = -1;
        __syncthreads();
        for (int i = tid; i < 2048; i += BLOCK)
            if (hist[i] >= cap) atomicMax(&s_best, i);
        __syncthreads();
        const int b1 = s_best;
        if (b1 < 0) { __syncthreads(); continue; }
        const int A1 = (b1 + 1 < 2048) ? hist[b1 + 1] : 0;
        const int cap2 = cap - A1;
        __syncthreads();

        for (int i = tid; i < 2048; i += BLOCK) hist[i] = 0;
        __syncthreads();
        for (int t = tid; t < ntok; t += BLOCK) {
            const float v = disp[(size_t)t * NE + e];
            if (v > 0.f) {
                const unsigned b = __float_as_uint(v);
                if ((int)(b >> 20) == b1) atomicAdd(&hist[(b >> 9) & 0x7FF], 1);
            }
        }
        __syncthreads();
        suffix_scan256(hist, 2048);
        if (tid == 0) s_best = -1;
        __syncthreads();
        for (int i = tid; i < 2048; i += BLOCK)
            if (hist[i] >= cap2) atomicMax(&s_best, i);
        __syncthreads();
        const int b2 = s_best;
        const int A2 = (b2 + 1 < 2048) ? hist[b2 + 1] : 0;
        const int cap3 = cap2 - A2;
        const unsigned key = ((unsigned)b1 << 11) | (unsigned)b2;
        __syncthreads();

        for (int i = tid; i < 512; i += BLOCK) hist[i] = 0;
        __syncthreads();
        for (int t = tid; t < ntok; t += BLOCK) {
            const float v = disp[(size_t)t * NE + e];
            if (v > 0.f) {
                const unsigned b = __float_as_uint(v);
                if ((b >> 9) == key) atomicAdd(&hist[b & 0x1FF], 1);
            }
        }
        __syncthreads();
        suffix_scan256(hist, 512);
        if (tid == 0) s_best = -1;
        __syncthreads();
        for (int i = tid; i < 512; i += BLOCK)
            if (hist[i] >= cap3) atomicMax(&s_best, i);
        __syncthreads();
        const int b3 = s_best;
        const int A3 = (b3 + 1 < 512) ? hist[b3 + 1] : 0;
        const int keep_eq = cap3 - A3;
        const unsigned thr = (key << 9) | (unsigned)b3;
        __syncthreads();

        int* s_ties = hist;
        if (tid == 0) s_tiecnt = 0;
        __syncthreads();
        for (int t = tid; t < ntok; t += BLOCK) {
            const size_t o = (size_t)t * NE + e;
            const float v = disp[o];
            if (v > 0.f) {
                const unsigned b = __float_as_uint(v);
                if (b < thr) {
                    disp[o] = 0.f;
                } else if (b == thr) {
                    const int p = atomicAdd(&s_tiecnt, 1);
                    if (p < 2048) s_ties[p] = t;
                }
            }
        }
        __syncthreads();
        const int tc = (s_tiecnt < 2048) ? s_tiecnt : 2048;
        if (s_tiecnt > keep_eq) {
            for (int i = tid; i < tc; i += BLOCK) {
                const int ti = s_ties[i];
                int rank = 0;
                for (int j = 0; j < tc; j++) rank += (s_ties[j] < ti);
                if (rank >= keep_eq) disp[(size_t)ti * NE + e] = 0.f;
            }
        }
        __syncthreads();
    }
}

extern "C" void kernel_launch(void* const* d_in, const int* in_sizes, int n_in,
                              void* d_out, int out_size)
{
    const float* hs = (const float*)d_in[0];
    const float* rw = (const float*)d_in[1];
    int hsize = in_sizes[0];
    if (n_in >= 2 && in_sizes[0] < in_sizes[1]) {
        hs = (const float*)d_in[1];
        rw = (const float*)d_in[0];
        hsize = in_sizes[1];
    }
    const int ntok = hsize / HDIM;

    float* out   = (float*)d_out;
    float* disp  = out;                          // [N, E]
    float* loss  = out + (size_t)ntok * NE;      // scalar
    float* probs = loss + 1;                     // [N, E]

    cudaFuncSetAttribute(route_fused, cudaFuncAttributeMaxDynamicSharedMemorySize, DYN_SMEM);
    route_fused<<<GRID, BLOCK, DYN_SMEM>>>(hs, rw, disp, probs, loss, ntok);
}

// round 17
// speedup vs baseline: 1.4768x; 1.4200x over previous
#include <cuda_runtime.h>
#include <cstdint>

#define GRID   148
#define BLOCK  128
#define NWARP  (BLOCK / 32)
#define NE     8
#define HDIM   1024

#define SW_BYTES    (NE * HDIM * 4)      // 32 KB weights
#define GROUP_BYTES 16384                // 4 token rows x 4 KB
#define DYN_SMEM    (SW_BYTES + NWARP * 2 * GROUP_BYTES)   // 160 KB

__device__ float g_partials[GRID * 16];
__device__ int   g_ticket = 0;

// Packed fp32x2 FMA (Blackwell): d.lo += a.lo*b.lo ; d.hi += a.hi*b.hi
#define FMA2(d, a, b) asm("fma.rn.f32x2 %0, %1, %2, %0;" : "+l"(d) : "l"(a), "l"(b))

__device__ __forceinline__ uint32_t smem_u32(const void* p) {
    return (uint32_t)__cvta_generic_to_shared(p);
}

#define MBAR_INIT(addr, cnt) \
    asm volatile("mbarrier.init.shared.b64 [%0], %1;" :: "r"(addr), "r"(cnt) : "memory")
#define MBAR_EXPECT_TX(addr, bytes) \
    asm volatile("mbarrier.arrive.expect_tx.shared.b64 _, [%0], %1;" :: "r"(addr), "r"(bytes) : "memory")
#define BULK_G2S(dst, src, bytes, mbar) \
    asm volatile("cp.async.bulk.shared::cta.global.mbarrier::complete_tx::bytes [%0], [%1], %2, [%3];" \
                 :: "r"(dst), "l"(src), "r"(bytes), "r"(mbar) : "memory")

__device__ __forceinline__ void mbar_wait(uint32_t mbar, uint32_t parity)
{
    asm volatile(
        "{\n\t"
        ".reg .pred P;\n\t"
        "WAIT_%=:\n\t"
        "mbarrier.try_wait.parity.acquire.cta.shared::cta.b64 P, [%0], %1, 0x989680;\n\t"
        "@P bra.uni DONE_%=;\n\t"
        "bra.uni WAIT_%=;\n\t"
        "DONE_%=:\n\t"
        "}"
        :: "r"(mbar), "r"(parity) : "memory");
}

__device__ __forceinline__ void suffix_scan_fin(int* h, int n)
{
    // inclusive suffix sums, n <= 2048, BLOCK=128 threads
    for (int off = 1; off < n; off <<= 1) {
        int v[16]; int c = 0;
        for (int i = threadIdx.x; i < n; i += BLOCK) {
            const int add = (i + off < n) ? h[i + off] : 0;
            v[c++] = h[i] + add;
        }
        __syncthreads();
        c = 0;
        for (int i = threadIdx.x; i < n; i += BLOCK) h[i] = v[c++];
        __syncthreads();
    }
}

__global__ void __launch_bounds__(BLOCK, 1)
route_fused(const float* __restrict__ hs, const float* __restrict__ rw,
            float* __restrict__ disp, float* __restrict__ probs,
            float* __restrict__ loss_out, int ntok)
{
    extern __shared__ __align__(16) char dynsmem[];
    float* sw = (float*)dynsmem;                         // 32 KB weights / finalize hist
    char*  hbuf = dynsmem + SW_BYTES;                    // NWARP x 2 x 16 KB ring buffers

    __shared__ __align__(8) unsigned long long mbar_store[NWARP][2];
    __shared__ float sW[NWARP][NE];
    __shared__ float sP[NWARP][NE];
    __shared__ float red[NWARP][16];
    __shared__ float sSum[16];
    __shared__ int   s_best, s_tiecnt, s_last;
    __shared__ unsigned s_over;

    // Stage router weights (32KB) into SMEM; init per-warp barrier pairs
    {
        const float4* src = (const float4*)rw;
        float4* dst = (float4*)sw;
        for (int i = threadIdx.x; i < NE * HDIM / 4; i += BLOCK) dst[i] = src[i];
    }
    if (threadIdx.x < NWARP * 2)
        MBAR_INIT(smem_u32(&mbar_store[threadIdx.x >> 1][threadIdx.x & 1]), 1);
    __syncthreads();

    const int warp = threadIdx.x >> 5;
    const int lane = threadIdx.x & 31;
    const int gwarp = blockIdx.x * NWARP + warp;
    const int nwarps = GRID * NWARP;
    const int ngroups = (ntok + 3) >> 2;      // 4 tokens per warp-iteration

    const ulonglong2* __restrict__ hs2 = (const ulonglong2*)hs;  // 256 x 16B per row
    const ulonglong2* __restrict__ w2  = (const ulonglong2*)sw;

    char* const buf0 = hbuf + (warp * 2 + 0) * GROUP_BYTES;
    char* const buf1 = hbuf + (warp * 2 + 1) * GROUP_BYTES;
    const uint32_t mb0 = smem_u32(&mbar_store[warp][0]);
    const uint32_t mb1 = smem_u32(&mbar_store[warp][1]);

    float accW = 0.f;
    float accP = 0.f;
    unsigned ph0 = 0, ph1 = 0;

    // ---- prologue: bulk-stage this warp's first two groups (if full) ----
    if (lane == 0) {
        const int ga = gwarp, gb = gwarp + nwarps;
        if (ga < ngroups && ((ga << 2) + 4) <= ntok) {
            MBAR_EXPECT_TX(mb0, GROUP_BYTES);
            BULK_G2S(smem_u32(buf0), (const char*)(hs2 + (size_t)(ga << 2) * (HDIM / 4)),
                     GROUP_BYTES, mb0);
        }
        if (gb < ngroups && ((gb << 2) + 4) <= ntok) {
            MBAR_EXPECT_TX(mb1, GROUP_BYTES);
            BULK_G2S(smem_u32(buf1), (const char*)(hs2 + (size_t)(gb << 2) * (HDIM / 4)),
                     GROUP_BYTES, mb1);
        }
    }
    __syncwarp();

    int k = 0;   // per-warp group ordinal; buffer = k & 1
    for (int g = gwarp; g < ngroups; g += nwarps, k++) {
        const int t0 = g << 2;
        const int tcount = (t0 + 4 <= ntok) ? 4 : (ntok - t0);
        const int b = k & 1;
        char* const buf = b ? buf1 : buf0;
        const uint32_t mb = b ? mb1 : mb0;

        unsigned long long acc[4][NE];    // 64 regs
        #pragma unroll
        for (int t = 0; t < 4; t++)
            #pragma unroll
            for (int e = 0; e < NE; e++) acc[t][e] = 0ull;

        if (tcount == 4) {
            mbar_wait(mb, b ? ph1 : ph0);
            if (b) ph1 ^= 1; else ph0 ^= 1;

            // mainloop on staged data — FMA2 order identical to R12 (bit-exact)
            #pragma unroll
            for (int c = 0; c < HDIM / 128; c++) {
                const ulonglong2* sp = (const ulonglong2*)(buf + c * 512 + lane * 16);
                ulonglong2 h[4];
                #pragma unroll
                for (int t = 0; t < 4; t++) h[t] = sp[t * 256];   // t*4096 bytes

                const int off = c * 32 + lane;
                #pragma unroll
                for (int e = 0; e < NE; e++) {
                    const ulonglong2 w = w2[e * (HDIM / 4) + off];
                    #pragma unroll
                    for (int t = 0; t < 4; t++) {
                        FMA2(acc[t][e], h[t].x, w.x);
                        FMA2(acc[t][e], h[t].y, w.y);
                    }
                }
            }
            __syncwarp();

            // refill this buffer with the group two strides ahead
            if (lane == 0) {
                const int gnn = g + 2 * nwarps;
                if (gnn < ngroups && ((gnn << 2) + 4) <= ntok) {
                    MBAR_EXPECT_TX(mb, GROUP_BYTES);
                    BULK_G2S(smem_u32(buf),
                             (const char*)(hs2 + (size_t)(gnn << 2) * (HDIM / 4)),
                             GROUP_BYTES, mb);
                }
            }

            // ---- epilogue: identical to R12 ----
            float a[32];
            #pragma unroll
            for (int t = 0; t < 4; t++)
                #pragma unroll
                for (int e = 0; e < NE; e++) {
                    const unsigned long long v = acc[t][e];
                    a[t * NE + e] = __uint_as_float((unsigned)v) +
                                    __uint_as_float((unsigned)(v >> 32));
                }

            #pragma unroll
            for (int s = 16; s > 0; s >>= 1) {
                const bool hi = (lane & s) != 0;
                #pragma unroll
                for (int j = 0; j < 32; j++) {
                    if (j >= s) break;
                    const float give = hi ? a[j] : a[j + s];
                    const float got  = __shfl_xor_sync(0xffffffffu, give, s);
                    const float keep = hi ? a[j + s] : a[j];
                    a[j] = keep + got;
                }
            }
            const float l_own = a[0];
            const int   e_own = lane & 7;
            const int   base  = lane & ~7;

            float ls[NE];
            #pragma unroll
            for (int e = 0; e < NE; e++)
                ls[e] = __shfl_sync(0xffffffffu, l_own, base | e);
            float mx = ls[0];
            #pragma unroll
            for (int e = 1; e < NE; e++) mx = fmaxf(mx, ls[e]);

            const float ex_own = expf(l_own - mx);
            float ex[NE], sum = 0.f;
            #pragma unroll
            for (int e = 0; e < NE; e++) {
                ex[e] = __shfl_sync(0xffffffffu, ex_own, base | e);
                sum += ex[e];
            }
            const float inv = 1.f / sum;
            float p[NE];
            #pragma unroll
            for (int e = 0; e < NE; e++) p[e] = ex[e] * inv;

            int i1 = 0;
            #pragma unroll
            for (int e = 1; e < NE; e++) if (p[e] > p[i1]) i1 = e;
            int i2 = -1;
            #pragma unroll
            for (int e = 0; e < NE; e++)
                if (e != i1 && (i2 < 0 || p[e] > p[i2])) i2 = e;
            const float dsum = p[i1] + p[i2];
            const float d1 = p[i1] / dsum;
            const float d2 = p[i2] / dsum;

            const float p_own = p[e_own];
            const float dm = (e_own == i1) ? d1 : (e_own == i2) ? d2 : 0.f;
            const size_t o = (size_t)t0 * NE + lane;
            probs[o] = p_own;
            disp[o]  = dm;
            accP += p_own;
            accW += dm;
        } else {
            // tail (<4 tokens): direct-LDG path (same per-token math as R12)
            const ulonglong2* __restrict__ h0 = hs2 + (size_t)t0 * (HDIM / 4);
            for (int c = 0; c < HDIM / 128; c++) {
                const int off = c * 32 + lane;
                for (int t = 0; t < tcount; t++) {
                    const ulonglong2 h = h0[t * (HDIM / 4) + off];
                    #pragma unroll
                    for (int e = 0; e < NE; e++) {
                        const ulonglong2 w = w2[e * (HDIM / 4) + off];
                        FMA2(acc[t][e], h.x, w.x);
                        FMA2(acc[t][e], h.y, w.y);
                    }
                }
            }
            for (int t = 0; t < tcount; t++) {
                float l[NE];
                #pragma unroll
                for (int e = 0; e < NE; e++) {
                    const unsigned long long v = acc[t][e];
                    l[e] = __uint_as_float((unsigned)v) + __uint_as_float((unsigned)(v >> 32));
                }
                #pragma unroll
                for (int s = 16; s > 0; s >>= 1)
                    #pragma unroll
                    for (int e = 0; e < NE; e++)
                        l[e] += __shfl_xor_sync(0xffffffffu, l[e], s);
                float mx = l[0];
                #pragma unroll
                for (int e = 1; e < NE; e++) mx = fmaxf(mx, l[e]);
                float ex[NE], sum = 0.f;
                #pragma unroll
                for (int e = 0; e < NE; e++) { ex[e] = expf(l[e] - mx); sum += ex[e]; }
                const float inv = 1.f / sum;
                float p[NE];
                #pragma unroll
                for (int e = 0; e < NE; e++) p[e] = ex[e] * inv;
                int i1 = 0;
                #pragma unroll
                for (int e = 1; e < NE; e++) if (p[e] > p[i1]) i1 = e;
                int i2 = -1;
                #pragma unroll
                for (int e = 0; e < NE; e++)
                    if (e != i1 && (i2 < 0 || p[e] > p[i2])) i2 = e;
                const float dsum = p[i1] + p[i2];
                const float d1 = p[i1] / dsum;
                const float d2 = p[i2] / dsum;
                if (lane < NE) {
                    const size_t o = (size_t)(t0 + t) * NE + lane;
                    probs[o] = p[lane];
                    const float dm = (lane == i1) ? d1 : (lane == i2) ? d2 : 0.f;
                    disp[o] = dm;
                    accP += p[lane];
                    accW += dm;
                }
            }
        }
    }

    // combine lanes sharing the same expert (xor over token bits 3,4)
    accW += __shfl_xor_sync(0xffffffffu, accW, 8);
    accW += __shfl_xor_sync(0xffffffffu, accW, 16);
    accP += __shfl_xor_sync(0xffffffffu, accP, 8);
    accP += __shfl_xor_sync(0xffffffffu, accP, 16);

    if (lane < NE) { sW[warp][lane] = accW; sP[warp][lane] = accP; }
    __syncthreads();
    if (threadIdx.x < 16) {
        const int e = threadIdx.x & 7;
        float s = 0.f;
        if (threadIdx.x < 8) {
            #pragma unroll
            for (int w = 0; w < NWARP; w++) s += sW[w][e];
        } else {
            #pragma unroll
            for (int w = 0; w < NWARP; w++) s += sP[w][e];
        }
        g_partials[blockIdx.x * 16 + threadIdx.x] = s;
    }
    __syncthreads();

    // ---- last-block election ----
    if (threadIdx.x == 0) {
        __threadfence();
        const int old = atomicAdd(&g_ticket, 1);
        s_last = (old == GRID - 1);
        if (s_last) g_ticket = 0;
    }
    __syncthreads();
    if (!s_last) return;

    // =================== finalize (last block only, 128 threads) ===================
    const int tid = threadIdx.x;
    int* hist = (int*)sw;            // weights no longer needed: reuse as hist/ties
    {
        float s = 0.f;
        for (int i = tid; i < GRID * 16; i += BLOCK) s += g_partials[i];
        s += __shfl_xor_sync(0xffffffffu, s, 16);
        if (lane < 16) red[warp][lane] = s;
    }
    __syncthreads();
    if (tid < 16) {
        float s = 0.f;
        #pragma unroll
        for (int w = 0; w < NWARP; w++) s += red[w][tid];
        sSum[tid] = s;
    }
    __syncthreads();

    const int cap = (int)(1.25 * (double)ntok / (double)NE);

    if (tid == 0) {
        float l = 0.f;
        for (int e = 0; e < NE; e++) l += sSum[e] * sSum[8 + e];
        loss_out[0] = 0.01f * (l / (float)ntok);
        unsigned m = 0;
        for (int e = 0; e < NE; e++)
            if (sSum[e] > (float)cap) m |= 1u << e;
        s_over = m;
    }
    __syncthreads();
    const unsigned over = s_over;
    if (!over) return;

    for (int e = 0; e < NE; e++) {
        if (!((over >> e) & 1u)) continue;

        for (int i = tid; i < 2048; i += BLOCK) hist[i] = 0;
        __syncthreads();
        for (int t = tid; t < ntok; t += BLOCK) {
            const float v = disp[(size_t)t * NE + e];
            if (v > 0.f) atomicAdd(&hist[__float_as_uint(v) >> 20], 1);
        }
        __syncthreads();
        suffix_scan_fin(hist, 2048);
        if (tid == 0) s_best = -1;
        __syncthreads();
        for (int i = tid; i < 2048; i += BLOCK)
            if (hist[i] >= cap) atomicMax(&s_best, i);
        __syncthreads();
        const int b1 = s_best;
        if (b1 < 0) { __syncthreads(); continue; }
        const int A1 = (b1 + 1 < 2048) ? hist[b1 + 1] : 0;
        const int cap2 = cap - A1;
        __syncthreads();

        for (int i = tid; i < 2048; i += BLOCK) hist[i] = 0;
        __syncthreads();
        for (int t = tid; t < ntok; t += BLOCK) {
            const float v = disp[(size_t)t * NE + e];
            if (v > 0.f) {
                const unsigned b = __float_as_uint(v);
                if ((int)(b >> 20) == b1) atomicAdd(&hist[(b >> 9) & 0x7FF], 1);
            }
        }
        __syncthreads();
        suffix_scan_fin(hist, 2048);
        if (tid == 0) s_best = -1;
        __syncthreads();
        for (int i = tid; i < 2048; i += BLOCK)
            if (hist[i] >= cap2) atomicMax(&s_best, i);
        __syncthreads();
        const int b2 = s_best;
        const int A2 = (b2 + 1 < 2048) ? hist[b2 + 1] : 0;
        const int cap3 = cap2 - A2;
        const unsigned key = ((unsigned)b1 << 11) | (unsigned)b2;
        __syncthreads();

        for (int i = tid; i < 512; i += BLOCK) hist[i] = 0;
        __syncthreads();
        for (int t = tid; t < ntok; t += BLOCK) {
            const float v = disp[(size_t)t * NE + e];
            if (v > 0.f) {
                const unsigned b = __float_as_uint(v);
                if ((b >> 9) == key) atomicAdd(&hist[b & 0x1FF], 1);
            }
        }
        __syncthreads();
        suffix_scan_fin(hist, 512);
        if (tid == 0) s_best = -1;
        __syncthreads();
        for (int i = tid; i < 512; i += BLOCK)
            if (hist[i] >= cap3) atomicMax(&s_best, i);
        __syncthreads();
        const int b3 = s_best;
        const int A3 = (b3 + 1 < 512) ? hist[b3 + 1] : 0;
        const int keep_eq = cap3 - A3;
        const unsigned thr = (key << 9) | (unsigned)b3;
        __syncthreads();

        int* s_ties = hist;
        if (tid == 0) s_tiecnt = 0;
        __syncthreads();
        for (int t = tid; t < ntok; t += BLOCK) {
            const size_t o = (size_t)t * NE + e;
            const float v = disp[o];
            if (v > 0.f) {
                const unsigned b = __float_as_uint(v);
                if (b < thr) {
                    disp[o] = 0.f;
                } else if (b == thr) {
                    const int p = atomicAdd(&s_tiecnt, 1);
                    if (p < 2048) s_ties[p] = t;
                }
            }
        }
        __syncthreads();
        const int tc = (s_tiecnt < 2048) ? s_tiecnt : 2048;
        if (s_tiecnt > keep_eq) {
            for (int i = tid; i < tc; i += BLOCK) {
                const int ti = s_ties[i];
                int rank = 0;
                for (int j = 0; j < tc; j++) rank += (s_ties[j] < ti);
                if (rank >= keep_eq) disp[(size_t)ti * NE + e] = 0.f;
            }
        }
        __syncthreads();
    }
}

extern "C" void kernel_launch(void* const* d_in, const int* in_sizes, int n_in,
                              void* d_out, int out_size)
{
    const float* hs = (const float*)d_in[0];
    const float* rw = (const float*)d_in[1];
    int hsize = in_sizes[0];
    if (n_in >= 2 && in_sizes[0] < in_sizes[1]) {
        hs = (const float*)d_in[1];
        rw = (const float*)d_in[0];
        hsize = in_sizes[1];
    }
    const int ntok = hsize / HDIM;

    float* out   = (float*)d_out;
    float* disp  = out;                          // [N, E]
    float* loss  = out + (size_t)ntok * NE;      // scalar
    float* probs = loss + 1;                     // [N, E]

    cudaFuncSetAttribute(route_fused, cudaFuncAttributeMaxDynamicSharedMemorySize, DYN_SMEM);
    route_fused<<<GRID, BLOCK, DYN_SMEM>>>(hs, rw, disp, probs, loss, ntok);
}